// round 4
// baseline (speedup 1.0000x reference)
#include <cuda_runtime.h>
#include <cuda_bf16.h>
#include <math.h>
#include <stdint.h>

#define N_SEQS   2048
#define SEQ_LEN  512
#define N_AA     20
#define M_MI     100
#define N_PAIRS  4950                    // 100*99/2 upper triangle
#define OUT_PSSM 0
#define OUT_CONS (SEQ_LEN * N_AA)        // 10240
#define OUT_MI   (OUT_CONS + SEQ_LEN)    // 10752
#define OUT_TOTAL (OUT_MI + SEQ_LEN * SEQ_LEN)  // 272896

// Scratch (no dynamic allocation allowed)
__device__ unsigned char g_colpack[128 * N_SEQS];    // column-major int8 msa[:, :128] (100 used)
__device__ int           g_counts[SEQ_LEN * 21];     // per-position AA counts (incl gap)

// ---------------------------------------------------------------------------
// Pack columns 0..99 into int8 column-major (coalesced reads, lane = column)
// AND zero the MI output region + g_counts (replaces two memset nodes).
// grid (4, 32) x 256 = 32768 threads.
// ---------------------------------------------------------------------------
__global__ __launch_bounds__(256) void pack_kernel(const int* __restrict__ msa,
                                                   float* __restrict__ out) {
    int tid = threadIdx.x, lane = tid & 31, w = tid >> 5;

    // Zero MI region (512*512 floats = 65536 float4) + counts
    int gtid = (blockIdx.y * 4 + blockIdx.x) * 256 + tid;
    float4* o4 = (float4*)(out + OUT_MI);
    float4 z = make_float4(0.f, 0.f, 0.f, 0.f);
    o4[gtid] = z;
    o4[gtid + 32768] = z;
    if (gtid < SEQ_LEN * 21) g_counts[gtid] = 0;

    int col   = blockIdx.x * 32 + lane;
    int rbase = blockIdx.y * 64 + w * 8;
    bool dopack = (col < M_MI);

    uint32_t p0 = 0, p1 = 0;
#pragma unroll
    for (int s = 0; s < 4; s++) {
        p0 |= (uint32_t)msa[(rbase + s)     * SEQ_LEN + col] << (8 * s);
        p1 |= (uint32_t)msa[(rbase + 4 + s) * SEQ_LEN + col] << (8 * s);
    }
    if (dopack) {
        *(uint32_t*)&g_colpack[col * N_SEQS + rbase]     = p0;
        *(uint32_t*)&g_colpack[col * N_SEQS + rbase + 4] = p1;
    }
}

// ---------------------------------------------------------------------------
// Per-position AA counts: per-warp replica histograms -> no atomics in the
// hot loop. grid (16, 16) x 256.
// ---------------------------------------------------------------------------
__global__ __launch_bounds__(256) void count_kernel(const int* __restrict__ msa) {
    __shared__ int cnt[8][32][21];     // [warp][lane(col)][symbol]
    int tid = threadIdx.x, lane = tid & 31, w = tid >> 5;
    for (int v = tid; v < 8 * 32 * 21; v += 256) ((int*)cnt)[v] = 0;
    __syncthreads();

    int col   = blockIdx.x * 32 + lane;
    int rbase = blockIdx.y * 128 + w * 16;
    int* my = cnt[w][lane];
#pragma unroll
    for (int s = 0; s < 16; s++) {
        int c = msa[(rbase + s) * SEQ_LEN + col];   // coalesced 128B per warp
        my[c] += 1;                                  // private: plain RMW
    }
    __syncthreads();

    for (int v = tid; v < 32 * 21; v += 256) {
        int l = v / 21, c = v % 21;
        int s = 0;
#pragma unroll
        for (int ww = 0; ww < 8; ww++) s += cnt[ww][l][c];
        if (s) atomicAdd(&g_counts[(blockIdx.x * 32 + l) * 21 + c], s);
    }
}

// ---------------------------------------------------------------------------
// PSSM + conservation: one warp per position (lane = amino acid).
// ---------------------------------------------------------------------------
__global__ __launch_bounds__(256) void pssm_kernel(float* __restrict__ out, const float* __restrict__ pc) {
    int gtid = blockIdx.x * blockDim.x + threadIdx.x;
    int p = gtid >> 5, lane = gtid & 31;
    if (p >= SEQ_LEN) return;

    int ct = (lane < 20) ? g_counts[p * 21 + lane] : 0;

    int t = ct;
#pragma unroll
    for (int off = 16; off; off >>= 1) t += __shfl_xor_sync(0xffffffffu, t, off);
    int total = t;

    float pcount = 0.01f * pc[0];
    float inv_den = 1.0f / ((float)N_SEQS + pcount * 20.0f);
    float tinv = 1.0f / fmaxf((float)total, 1.0f);

    float ent = 0.0f;
    if (lane < 20) {
        float freq = ((float)ct + pcount) * inv_den;
        out[OUT_PSSM + p * 20 + lane] = logf(freq * 20.0f + 1e-10f);
        float f = (float)ct * tinv;
        ent = -f * log2f(f + 1e-10f);
    }
#pragma unroll
    for (int off = 16; off; off >>= 1) ent += __shfl_xor_sync(0xffffffffu, ent, off);
    if (lane == 0)
        out[OUT_CONS + p] = (total > 0) ? (1.0f - ent * (1.0f / 4.321928094887362f)) : 0.0f;
}

// ---------------------------------------------------------------------------
// MI: TWO warps per (i<j) pair (each handles 1024 sequences into a private
// 441-bin histogram; merged for free in the epilogue). 441 bins = a*21+b,
// no gap predicate: gap events land in ignored bins (single IMAD per event).
// 4 pairs per 256-thread CTA; grid 1238 -> ~9900 warps (full machine).
// Integer log2 LUT -> no MUFU in the epilogue.
// ---------------------------------------------------------------------------
__global__ __launch_bounds__(256, 8) void mi_kernel(float* __restrict__ mi_out) {
    __shared__ int   hist[8][441];
    __shared__ float lut[2049];       // log2(0..2048)
    __shared__ float slra[4][20];
    __shared__ float slcb[4][20];

    int tid = threadIdx.x, wid = tid >> 5, lane = tid & 31;
    int slot = wid >> 1;              // pair slot 0..3 within CTA
    int half = wid & 1;               // which 1024-seq half this warp owns
    for (int v = tid; v < 2049; v += 256) lut[v] = log2f((float)v);

    int pid = blockIdx.x * 4 + slot;
    bool valid = (pid < N_PAIRS);

    int i = 0, j = 0;
    if (valid) {
        // Decode upper-triangle pair index -> (i, j), i < j; T(i) = i*(199-i)/2
        float d = sqrtf(39601.0f - 8.0f * (float)pid);
        i = (int)((199.0f - d) * 0.5f);
        if (i < 0) i = 0;
        if (i > 98) i = 98;
        while ((((i + 1) * (199 - (i + 1))) >> 1) <= pid) ++i;
        while (((i * (199 - i)) >> 1) > pid) --i;
        j = pid - ((i * (199 - i)) >> 1) + i + 1;
    }

    int* h = hist[wid];
    for (int v = lane; v < 441; v += 32) h[v] = 0;
    __syncthreads();                  // lut + all hists ready

    if (valid) {
        const uint4* ca = (const uint4*)(g_colpack + i * N_SEQS + half * 1024);
        const uint4* cb = (const uint4*)(g_colpack + j * N_SEQS + half * 1024);
#pragma unroll
        for (int it = 0; it < 2; it++) {          // 2 x LDG.128 per operand
            uint4 va = ca[lane + 32 * it];
            uint4 vb = cb[lane + 32 * it];
            const uint32_t wa_[4] = {va.x, va.y, va.z, va.w};
            const uint32_t wb_[4] = {vb.x, vb.y, vb.z, vb.w};
#pragma unroll
            for (int q = 0; q < 4; q++) {
                uint32_t wa = wa_[q], wb = wb_[q];
#pragma unroll
                for (int s = 0; s < 4; s++) {
                    int a = (wa >> (8 * s)) & 255;
                    int b = (wb >> (8 * s)) & 255;
                    atomicAdd(&h[a * 21 + b], 1);   // code = a*21+b, no predicate
                }
            }
        }
    }
    __syncthreads();                  // both halves of every pair complete

    if (valid && half == 0) {
        const int* h0 = hist[wid];
        const int* h1 = hist[wid + 1];

        // Integer marginals over the 20x20 non-gap block (merged halves)
        int rs = 0, cs = 0;
        if (lane < 20) {
#pragma unroll
            for (int b = 0; b < 20; b++) {
                rs += h0[lane * 21 + b] + h1[lane * 21 + b];
                cs += h0[b * 21 + lane] + h1[b * 21 + lane];
            }
            slra[slot][lane] = lut[rs];
            slcb[slot][lane] = lut[cs];
        }
        int tv = (lane < 20) ? rs : 0;
#pragma unroll
        for (int off = 16; off; off >>= 1) tv += __shfl_xor_sync(0xffffffffu, tv, off);
        int tot = tv;
        __syncwarp();

        int tots = (tot > 0) ? tot : 1;
        float lt = lut[tots];
        float acc = 0.0f;
        for (int c = lane; c < 400; c += 32) {
            int a = (c * 3277) >> 16;   // c / 20 for c < 400
            int b = c - a * 20;
            int idx = a * 21 + b;
            int H = h0[idx] + h1[idx];
            if (H > 0)
                acc += (float)H * (lut[H] - slra[slot][a] - slcb[slot][b] + lt);
        }
#pragma unroll
        for (int off = 16; off; off >>= 1) acc += __shfl_xor_sync(0xffffffffu, acc, off);

        if (lane == 0) {
            float mi = (tot > 0) ? acc / (float)tots : 0.0f;
            mi_out[i * SEQ_LEN + j] = mi;
            mi_out[j * SEQ_LEN + i] = mi;
        }
    }
}

// ---------------------------------------------------------------------------
// Launch: pack(+zero) -> fork -> [mi on main] || [count + pssm on side] -> join
// ---------------------------------------------------------------------------
extern "C" void kernel_launch(void* const* d_in, const int* in_sizes, int n_in,
                              void* d_out, int out_size) {
    const int*   msa = (const int*)d_in[0];
    const float* pc  = (const float*)d_in[1];
    float*       out = (float*)d_out;

    static cudaStream_t s1;
    static cudaEvent_t e_fork, e_join;
    static bool init = false;
    if (!init) {
        cudaStreamCreateWithFlags(&s1, cudaStreamNonBlocking);
        cudaEventCreateWithFlags(&e_fork, cudaEventDisableTiming);
        cudaEventCreateWithFlags(&e_join, cudaEventDisableTiming);
        init = true;
    }

    pack_kernel<<<dim3(4, 32), 256>>>(msa, out);    // pack + zero MI region + counts
    cudaEventRecord(e_fork, 0);

    cudaStreamWaitEvent(s1, e_fork, 0);
    count_kernel<<<dim3(16, 16), 256, 0, s1>>>(msa);
    pssm_kernel<<<64, 256, 0, s1>>>(out, pc);
    cudaEventRecord(e_join, s1);

    mi_kernel<<<(N_PAIRS + 3) / 4, 256>>>(out + OUT_MI);
    cudaStreamWaitEvent(0, e_join, 0);
}